// round 5
// baseline (speedup 1.0000x reference)
#include <cuda_runtime.h>

#define HD 128
#define NMAX 100000
#define EMAX 1600000

// -------- scratch (device globals; no allocations allowed) --------
__device__ float g_deg[NMAX];
__device__ float g_dinv[NMAX];
__device__ float g_A[(size_t)NMAX * HD];   // GEMM output / gather source
__device__ float g_B[(size_t)NMAX * HD];   // aggregation accumulator
__device__ float g_as[NMAX];
__device__ float g_ad[NMAX];
__device__ float g_amax[NMAX];
__device__ float g_den[NMAX];

// -------- helpers --------
__device__ __forceinline__ float leaky(float x) { return x > 0.f ? x : 0.2f * x; }

__device__ __forceinline__ void redAdd4(float* p, float a, float b, float c, float d) {
    asm volatile("red.global.add.v4.f32 [%0], {%1,%2,%3,%4};"
                 :: "l"(p), "f"(a), "f"(b), "f"(c), "f"(d) : "memory");
}

__device__ __forceinline__ void atomicMaxF(float* addr, float v) {
    if (v >= 0.f) atomicMax((int*)addr, __float_as_int(v));
    else          atomicMin((unsigned int*)addr, __float_as_uint(v));
}

// -------- degree / normalization --------
__global__ void k_init_deg(int n) {
    int i = blockIdx.x * blockDim.x + threadIdx.x;
    if (i < n) g_deg[i] = 1.0f;   // self-loop weight 1
}

__global__ void k_deg_edges(const int* __restrict__ dst, const float* __restrict__ ew, int e) {
    int i = blockIdx.x * blockDim.x + threadIdx.x;
    if (i < e) atomicAdd(&g_deg[dst[i]], ew[i]);
}

__global__ void k_dinv(int n) {
    int i = blockIdx.x * blockDim.x + threadIdx.x;
    if (i < n) {
        float d = g_deg[i];
        g_dinv[i] = d > 0.f ? rsqrtf(d) : 0.f;
    }
}

// -------- GEMM: Y[n,128] = (RELU? relu(X) : X)[n,128] @ W[128,128] --------
template<bool RELU>
__global__ __launch_bounds__(256) void k_gemm128(const float* __restrict__ X,
                                                 const float* __restrict__ W,
                                                 float* __restrict__ Y, int n) {
    __shared__ float xs[64][132];
    const int t = threadIdx.x;
    const int row0 = blockIdx.x * 64;

    // load 64x128 X tile (float4), optional relu
    #pragma unroll
    for (int i = t; i < 64 * 32; i += 256) {
        int r = i >> 5, c4 = i & 31;
        int gr = row0 + r;
        float4 v = make_float4(0.f, 0.f, 0.f, 0.f);
        if (gr < n) v = *(const float4*)(X + (size_t)gr * HD + c4 * 4);
        if (RELU) {
            v.x = fmaxf(v.x, 0.f); v.y = fmaxf(v.y, 0.f);
            v.z = fmaxf(v.z, 0.f); v.w = fmaxf(v.w, 0.f);
        }
        *(float4*)&xs[r][c4 * 4] = v;
    }
    __syncthreads();

    const int cx = t & 31;   // column group (4 cols)
    const int ry = t >> 5;   // row group (8 rows each)

    float4 acc[8];
    #pragma unroll
    for (int j = 0; j < 8; j++) acc[j] = make_float4(0.f, 0.f, 0.f, 0.f);

    #pragma unroll 4
    for (int k0 = 0; k0 < HD; k0 += 4) {
        float4 w0 = *(const float4*)(W + (size_t)(k0 + 0) * HD + cx * 4);
        float4 w1 = *(const float4*)(W + (size_t)(k0 + 1) * HD + cx * 4);
        float4 w2 = *(const float4*)(W + (size_t)(k0 + 2) * HD + cx * 4);
        float4 w3 = *(const float4*)(W + (size_t)(k0 + 3) * HD + cx * 4);
        #pragma unroll
        for (int j = 0; j < 8; j++) {
            float4 xv = *(const float4*)&xs[ry * 8 + j][k0];
            acc[j].x = fmaf(xv.x, w0.x, acc[j].x);
            acc[j].y = fmaf(xv.x, w0.y, acc[j].y);
            acc[j].z = fmaf(xv.x, w0.z, acc[j].z);
            acc[j].w = fmaf(xv.x, w0.w, acc[j].w);
            acc[j].x = fmaf(xv.y, w1.x, acc[j].x);
            acc[j].y = fmaf(xv.y, w1.y, acc[j].y);
            acc[j].z = fmaf(xv.y, w1.z, acc[j].z);
            acc[j].w = fmaf(xv.y, w1.w, acc[j].w);
            acc[j].x = fmaf(xv.z, w2.x, acc[j].x);
            acc[j].y = fmaf(xv.z, w2.y, acc[j].y);
            acc[j].z = fmaf(xv.z, w2.z, acc[j].z);
            acc[j].w = fmaf(xv.z, w2.w, acc[j].w);
            acc[j].x = fmaf(xv.w, w3.x, acc[j].x);
            acc[j].y = fmaf(xv.w, w3.y, acc[j].y);
            acc[j].z = fmaf(xv.w, w3.z, acc[j].z);
            acc[j].w = fmaf(xv.w, w3.w, acc[j].w);
        }
    }

    #pragma unroll
    for (int j = 0; j < 8; j++) {
        int gr = row0 + ry * 8 + j;
        if (gr < n) *(float4*)(Y + (size_t)gr * HD + cx * 4) = acc[j];
    }
}

// -------- GCN: B = bias + dinv^2 * A  (self-loop term + bias) --------
__global__ void k_gcn_init(const float* __restrict__ bias, int n) {
    int idx = blockIdx.x * blockDim.x + threadIdx.x;
    if (idx >= n * 32) return;
    int i = idx >> 5, c4 = idx & 31;
    float di = g_dinv[i];
    float coef = di * di;
    float4 a = *(const float4*)(g_A + (size_t)i * HD + c4 * 4);
    float4 b = *(const float4*)(bias + c4 * 4);
    float4 o;
    o.x = b.x + coef * a.x;
    o.y = b.y + coef * a.y;
    o.z = b.z + coef * a.z;
    o.w = b.w + coef * a.w;
    *(float4*)(g_B + (size_t)i * HD + c4 * 4) = o;
}

// -------- GCN edge scatter: B[dst] += norm * A[src], warp per edge --------
__global__ void k_gcn_edges(const int* __restrict__ src, const int* __restrict__ dst,
                            const float* __restrict__ ew, int e) {
    int gw = (blockIdx.x * blockDim.x + threadIdx.x) >> 5;
    if (gw >= e) return;
    int lane = threadIdx.x & 31;
    int s = __ldg(&src[gw]);
    int d = __ldg(&dst[gw]);
    float coef = g_dinv[s] * __ldg(&ew[gw]) * g_dinv[d];
    float4 v = *(const float4*)(g_A + (size_t)s * HD + lane * 4);
    float* p = g_B + (size_t)d * HD + lane * 4;
    redAdd4(p, v.x * coef, v.y * coef, v.z * coef, v.w * coef);
}

// -------- GAT: per-node attention dot products --------
__global__ void k_dots(const float* __restrict__ asrc, const float* __restrict__ adst, int n) {
    int gw = (blockIdx.x * blockDim.x + threadIdx.x) >> 5;
    if (gw >= n) return;
    int lane = threadIdx.x & 31;
    float4 gv = *(const float4*)(g_A + (size_t)gw * HD + lane * 4);
    float4 s = *(const float4*)(asrc + lane * 4);
    float4 d = *(const float4*)(adst + lane * 4);
    float vs = gv.x * s.x + gv.y * s.y + gv.z * s.z + gv.w * s.w;
    float vd = gv.x * d.x + gv.y * d.y + gv.z * d.z + gv.w * d.w;
    #pragma unroll
    for (int o = 16; o; o >>= 1) {
        vs += __shfl_xor_sync(0xffffffffu, vs, o);
        vd += __shfl_xor_sync(0xffffffffu, vd, o);
    }
    if (lane == 0) { g_as[gw] = vs; g_ad[gw] = vd; }
}

__global__ void k_amax_init(int n) {
    int i = blockIdx.x * blockDim.x + threadIdx.x;
    if (i < n) g_amax[i] = leaky(g_as[i] + g_ad[i]);   // self-loop edge
}

__global__ void k_amax_edges(const int* __restrict__ src, const int* __restrict__ dst, int e) {
    int i = blockIdx.x * blockDim.x + threadIdx.x;
    if (i >= e) return;
    int s = src[i], d = dst[i];
    float a = leaky(g_as[s] + g_ad[d]);
    atomicMaxF(&g_amax[d], a);
}

__global__ void k_den_init(int n) {
    int i = blockIdx.x * blockDim.x + threadIdx.x;
    if (i < n) {
        float aself = leaky(g_as[i] + g_ad[i]);
        g_den[i] = expf(aself - g_amax[i]);   // self-loop contribution
    }
}

__global__ void k_den_edges(const int* __restrict__ src, const int* __restrict__ dst, int e) {
    int i = blockIdx.x * blockDim.x + threadIdx.x;
    if (i >= e) return;
    int s = src[i], d = dst[i];
    float a = leaky(g_as[s] + g_ad[d]);
    atomicAdd(&g_den[d], expf(a - g_amax[d]));
}

// -------- GAT init: B = bg + alpha_self * A --------
__global__ void k_gat_init(const float* __restrict__ bg, int n) {
    int idx = blockIdx.x * blockDim.x + threadIdx.x;
    if (idx >= n * 32) return;
    int i = idx >> 5, c4 = idx & 31;
    float aself = leaky(g_as[i] + g_ad[i]);
    float coef = expf(aself - g_amax[i]) / g_den[i];
    float4 a = *(const float4*)(g_A + (size_t)i * HD + c4 * 4);
    float4 b = *(const float4*)(bg + c4 * 4);
    float4 o;
    o.x = b.x + coef * a.x;
    o.y = b.y + coef * a.y;
    o.z = b.z + coef * a.z;
    o.w = b.w + coef * a.w;
    *(float4*)(g_B + (size_t)i * HD + c4 * 4) = o;
}

// -------- GAT edge scatter: B[dst] += alpha * A[src], warp per edge --------
__global__ void k_gat_edges(const int* __restrict__ src, const int* __restrict__ dst, int e) {
    int gw = (blockIdx.x * blockDim.x + threadIdx.x) >> 5;
    if (gw >= e) return;
    int lane = threadIdx.x & 31;
    int s = __ldg(&src[gw]);
    int d = __ldg(&dst[gw]);
    float a = leaky(g_as[s] + g_ad[d]);
    float coef = expf(a - g_amax[d]) / g_den[d];
    float4 v = *(const float4*)(g_A + (size_t)s * HD + lane * 4);
    float* p = g_B + (size_t)d * HD + lane * 4;
    redAdd4(p, v.x * coef, v.y * coef, v.z * coef, v.w * coef);
}

// -------- final: out[n,16] = relu(B) @ Wc + bc --------
__global__ __launch_bounds__(256) void k_out(const float* __restrict__ Wc,
                                             const float* __restrict__ bc,
                                             float* __restrict__ out, int n) {
    __shared__ float4 ws[512];   // Wc[128][16] as float4
    for (int i = threadIdx.x; i < 512; i += 256) ws[i] = ((const float4*)Wc)[i];
    __syncthreads();
    int i = blockIdx.x * blockDim.x + threadIdx.x;
    if (i >= n) return;
    float4 a0 = ((const float4*)bc)[0];
    float4 a1 = ((const float4*)bc)[1];
    float4 a2 = ((const float4*)bc)[2];
    float4 a3 = ((const float4*)bc)[3];
    const float4* brow = (const float4*)(g_B + (size_t)i * HD);
    #pragma unroll 4
    for (int k0 = 0; k0 < 32; k0++) {
        float4 v = brow[k0];
        v.x = fmaxf(v.x, 0.f); v.y = fmaxf(v.y, 0.f);
        v.z = fmaxf(v.z, 0.f); v.w = fmaxf(v.w, 0.f);
        float bvals[4] = {v.x, v.y, v.z, v.w};
        #pragma unroll
        for (int kk = 0; kk < 4; kk++) {
            float bv = bvals[kk];
            const float4* w = &ws[(k0 * 4 + kk) * 4];
            float4 w0 = w[0], w1 = w[1], w2 = w[2], w3 = w[3];
            a0.x = fmaf(bv, w0.x, a0.x); a0.y = fmaf(bv, w0.y, a0.y);
            a0.z = fmaf(bv, w0.z, a0.z); a0.w = fmaf(bv, w0.w, a0.w);
            a1.x = fmaf(bv, w1.x, a1.x); a1.y = fmaf(bv, w1.y, a1.y);
            a1.z = fmaf(bv, w1.z, a1.z); a1.w = fmaf(bv, w1.w, a1.w);
            a2.x = fmaf(bv, w2.x, a2.x); a2.y = fmaf(bv, w2.y, a2.y);
            a2.z = fmaf(bv, w2.z, a2.z); a2.w = fmaf(bv, w2.w, a2.w);
            a3.x = fmaf(bv, w3.x, a3.x); a3.y = fmaf(bv, w3.y, a3.y);
            a3.z = fmaf(bv, w3.z, a3.z); a3.w = fmaf(bv, w3.w, a3.w);
        }
    }
    float4* op = (float4*)(out + (size_t)i * 16);
    op[0] = a0; op[1] = a1; op[2] = a2; op[3] = a3;
}

static inline int ceildiv(int a, int b) { return (a + b - 1) / b; }

extern "C" void kernel_launch(void* const* d_in, const int* in_sizes, int n_in,
                              void* d_out, int out_size) {
    const float* x       = (const float*)d_in[0];
    const int*   ei      = (const int*)d_in[1];
    const float* ew      = (const float*)d_in[2];
    const float* W1      = (const float*)d_in[3];
    const float* b1      = (const float*)d_in[4];
    const float* W2      = (const float*)d_in[5];
    const float* b2      = (const float*)d_in[6];
    const float* Wg      = (const float*)d_in[7];
    const float* att_src = (const float*)d_in[8];
    const float* att_dst = (const float*)d_in[9];
    const float* bg      = (const float*)d_in[10];
    const float* Wc      = (const float*)d_in[11];
    const float* bc      = (const float*)d_in[12];

    int n = in_sizes[0] / HD;
    int e = in_sizes[2];
    const int* src = ei;
    const int* dst = ei + e;

    float *dA = nullptr, *dB = nullptr;
    cudaGetSymbolAddress((void**)&dA, g_A);
    cudaGetSymbolAddress((void**)&dB, g_B);

    const int tb = 256;
    const int gb = ceildiv(n, 64);

    // normalization
    k_init_deg<<<ceildiv(n, tb), tb>>>(n);
    k_deg_edges<<<ceildiv(e, tb), tb>>>(dst, ew, e);
    k_dinv<<<ceildiv(n, tb), tb>>>(n);

    // GCN layer 1
    k_gemm128<false><<<gb, 256>>>(x, W1, dA, n);
    k_gcn_init<<<ceildiv(n * 32, tb), tb>>>(b1, n);
    k_gcn_edges<<<ceildiv(e * 32, tb), tb>>>(src, dst, ew, e);

    // GCN layer 2 (relu fused into GEMM load)
    k_gemm128<true><<<gb, 256>>>(dB, W2, dA, n);
    k_gcn_init<<<ceildiv(n * 32, tb), tb>>>(b2, n);
    k_gcn_edges<<<ceildiv(e * 32, tb), tb>>>(src, dst, ew, e);

    // GAT
    k_gemm128<true><<<gb, 256>>>(dB, Wg, dA, n);                 // g = relu(h2) @ Wg
    k_dots<<<ceildiv(n * 32, tb), tb>>>(att_src, att_dst, n);
    k_amax_init<<<ceildiv(n, tb), tb>>>(n);
    k_amax_edges<<<ceildiv(e, tb), tb>>>(src, dst, e);
    k_den_init<<<ceildiv(n, tb), tb>>>(n);
    k_den_edges<<<ceildiv(e, tb), tb>>>(src, dst, e);
    k_gat_init<<<ceildiv(n * 32, tb), tb>>>(bg, n);
    k_gat_edges<<<ceildiv(e * 32, tb), tb>>>(src, dst, e);

    // classifier
    k_out<<<ceildiv(n, tb), tb>>>(Wc, bc, (float*)d_out, n);
}

// round 6
// speedup vs baseline: 2.0103x; 2.0103x over previous
#include <cuda_runtime.h>

#define HD 128
#define NMAX 100000
#define EMAX 1600000
#define SCAN_B 1024

// -------- scratch (device globals; no allocations allowed) --------
__device__ float g_deg[NMAX];
__device__ float g_dinv[NMAX];
__device__ float g_A[(size_t)NMAX * HD];   // GEMM output / gather source
__device__ float g_B[(size_t)NMAX * HD];   // aggregation output
__device__ float g_as[NMAX];
__device__ float g_ad[NMAX];
__device__ int   g_cnt[NMAX];
__device__ int   g_rowptr[NMAX + 1];
__device__ int   g_cur[NMAX + 1];
__device__ int   g_bsum[128];
__device__ int   g_csr_src[EMAX];
__device__ float g_csr_coef[EMAX];

// -------- helpers --------
__device__ __forceinline__ float leaky(float x) { return x > 0.f ? x : 0.2f * x; }

// ================= CSR build =================
__global__ void k_zero(int n) {
    int i = blockIdx.x * blockDim.x + threadIdx.x;
    if (i < n) { g_cnt[i] = 0; g_deg[i] = 1.0f; }   // self-loop weight 1
    if (i == 0) { g_rowptr[0] = 0; g_cur[0] = 0; }
}

__global__ void k_count_deg(const int* __restrict__ dst, const float* __restrict__ ew, int e) {
    int i = blockIdx.x * blockDim.x + threadIdx.x;
    if (i >= e) return;
    int d = dst[i];
    atomicAdd(&g_cnt[d], 1);
    atomicAdd(&g_deg[d], ew[i]);
}

__global__ __launch_bounds__(SCAN_B) void k_scan1(int n) {
    __shared__ int s[SCAN_B];
    int t = threadIdx.x;
    int g = blockIdx.x * SCAN_B + t;
    int v = (g < n) ? g_cnt[g] : 0;
    s[t] = v;
    __syncthreads();
    #pragma unroll
    for (int o = 1; o < SCAN_B; o <<= 1) {
        int x = (t >= o) ? s[t - o] : 0;
        __syncthreads();
        s[t] += x;
        __syncthreads();
    }
    if (g < n) g_rowptr[g + 1] = s[t];            // inclusive scan, block-local
    if (t == SCAN_B - 1) g_bsum[blockIdx.x] = s[t];
}

__global__ void k_scan2(int nb) {
    __shared__ int s[128];
    int t = threadIdx.x;
    int v = (t < nb) ? g_bsum[t] : 0;
    s[t] = v;
    __syncthreads();
    #pragma unroll
    for (int o = 1; o < 128; o <<= 1) {
        int x = (t >= o) ? s[t - o] : 0;
        __syncthreads();
        s[t] += x;
        __syncthreads();
    }
    if (t < nb) g_bsum[t] = s[t] - v;             // exclusive
}

__global__ void k_scan3_dinv(int n) {
    int i = blockIdx.x * blockDim.x + threadIdx.x;
    if (i >= n) return;
    int v = g_rowptr[i + 1] + g_bsum[i >> 10];
    g_rowptr[i + 1] = v;
    g_cur[i + 1] = v;
    float d = g_deg[i];
    g_dinv[i] = d > 0.f ? rsqrtf(d) : 0.f;
}

__global__ void k_fill(const int* __restrict__ src, const int* __restrict__ dst,
                       const float* __restrict__ ew, int e) {
    int i = blockIdx.x * blockDim.x + threadIdx.x;
    if (i >= e) return;
    int s = src[i], d = dst[i];
    int pos = atomicAdd(&g_cur[d], 1);
    g_csr_src[pos] = s;
    g_csr_coef[pos] = g_dinv[s] * ew[i] * g_dinv[d];
}

// ================= GEMM: Y = (relu?)X @ W, optional attention dots =================
template<bool RELU, bool DOTS>
__global__ __launch_bounds__(256) void k_gemm128(const float* __restrict__ X,
                                                 const float* __restrict__ W,
                                                 float* __restrict__ Y,
                                                 const float* __restrict__ asrc,
                                                 const float* __restrict__ adst,
                                                 int n) {
    __shared__ float xs[64][132];
    const int t = threadIdx.x;
    const int row0 = blockIdx.x * 64;

    #pragma unroll
    for (int i = t; i < 64 * 32; i += 256) {
        int r = i >> 5, c4 = i & 31;
        int gr = row0 + r;
        float4 v = make_float4(0.f, 0.f, 0.f, 0.f);
        if (gr < n) v = *(const float4*)(X + (size_t)gr * HD + c4 * 4);
        if (RELU) {
            v.x = fmaxf(v.x, 0.f); v.y = fmaxf(v.y, 0.f);
            v.z = fmaxf(v.z, 0.f); v.w = fmaxf(v.w, 0.f);
        }
        *(float4*)&xs[r][c4 * 4] = v;
    }
    __syncthreads();

    const int cx = t & 31;
    const int ry = t >> 5;

    float4 acc[8];
    #pragma unroll
    for (int j = 0; j < 8; j++) acc[j] = make_float4(0.f, 0.f, 0.f, 0.f);

    #pragma unroll 4
    for (int k0 = 0; k0 < HD; k0 += 4) {
        float4 w0 = *(const float4*)(W + (size_t)(k0 + 0) * HD + cx * 4);
        float4 w1 = *(const float4*)(W + (size_t)(k0 + 1) * HD + cx * 4);
        float4 w2 = *(const float4*)(W + (size_t)(k0 + 2) * HD + cx * 4);
        float4 w3 = *(const float4*)(W + (size_t)(k0 + 3) * HD + cx * 4);
        #pragma unroll
        for (int j = 0; j < 8; j++) {
            float4 xv = *(const float4*)&xs[ry * 8 + j][k0];
            acc[j].x = fmaf(xv.x, w0.x, acc[j].x);
            acc[j].y = fmaf(xv.x, w0.y, acc[j].y);
            acc[j].z = fmaf(xv.x, w0.z, acc[j].z);
            acc[j].w = fmaf(xv.x, w0.w, acc[j].w);
            acc[j].x = fmaf(xv.y, w1.x, acc[j].x);
            acc[j].y = fmaf(xv.y, w1.y, acc[j].y);
            acc[j].z = fmaf(xv.y, w1.z, acc[j].z);
            acc[j].w = fmaf(xv.y, w1.w, acc[j].w);
            acc[j].x = fmaf(xv.z, w2.x, acc[j].x);
            acc[j].y = fmaf(xv.z, w2.y, acc[j].y);
            acc[j].z = fmaf(xv.z, w2.z, acc[j].z);
            acc[j].w = fmaf(xv.z, w2.w, acc[j].w);
            acc[j].x = fmaf(xv.w, w3.x, acc[j].x);
            acc[j].y = fmaf(xv.w, w3.y, acc[j].y);
            acc[j].z = fmaf(xv.w, w3.z, acc[j].z);
            acc[j].w = fmaf(xv.w, w3.w, acc[j].w);
        }
    }

    float4 s4, d4;
    if (DOTS) {
        s4 = *(const float4*)(asrc + cx * 4);
        d4 = *(const float4*)(adst + cx * 4);
    }

    #pragma unroll
    for (int j = 0; j < 8; j++) {
        int gr = row0 + ry * 8 + j;
        if (gr < n) *(float4*)(Y + (size_t)gr * HD + cx * 4) = acc[j];
        if (DOTS) {
            float ps = acc[j].x * s4.x + acc[j].y * s4.y + acc[j].z * s4.z + acc[j].w * s4.w;
            float pd = acc[j].x * d4.x + acc[j].y * d4.y + acc[j].z * d4.z + acc[j].w * d4.w;
            #pragma unroll
            for (int o = 16; o; o >>= 1) {
                ps += __shfl_xor_sync(0xffffffffu, ps, o);
                pd += __shfl_xor_sync(0xffffffffu, pd, o);
            }
            if (cx == 0 && gr < n) { g_as[gr] = ps; g_ad[gr] = pd; }
        }
    }
}

// ================= GCN aggregation (gather, warp per dst node) =================
__global__ __launch_bounds__(256) void k_gcn_agg(const float* __restrict__ bias, int n) {
    int w = (blockIdx.x * blockDim.x + threadIdx.x) >> 5;
    if (w >= n) return;
    int lane = threadIdx.x & 31;
    int beg = g_rowptr[w], end = g_rowptr[w + 1];

    float di = g_dinv[w];
    float cself = di * di;
    float4 av = *(const float4*)(g_A + (size_t)w * HD + lane * 4);
    float4 b  = *(const float4*)(bias + lane * 4);
    float4 acc;
    acc.x = b.x + cself * av.x;
    acc.y = b.y + cself * av.y;
    acc.z = b.z + cself * av.z;
    acc.w = b.w + cself * av.w;

    for (int j0 = beg; j0 < end; j0 += 32) {
        int idx = j0 + lane;
        int s = 0; float c = 0.f;
        if (idx < end) { s = g_csr_src[idx]; c = g_csr_coef[idx]; }
        int m = min(32, end - j0);
        int j = 0;
        for (; j + 1 < m; j += 2) {
            int   s0 = __shfl_sync(0xffffffffu, s, j);
            float c0 = __shfl_sync(0xffffffffu, c, j);
            int   s1 = __shfl_sync(0xffffffffu, s, j + 1);
            float c1 = __shfl_sync(0xffffffffu, c, j + 1);
            float4 v0 = *(const float4*)(g_A + (size_t)s0 * HD + lane * 4);
            float4 v1 = *(const float4*)(g_A + (size_t)s1 * HD + lane * 4);
            acc.x = fmaf(c0, v0.x, acc.x); acc.y = fmaf(c0, v0.y, acc.y);
            acc.z = fmaf(c0, v0.z, acc.z); acc.w = fmaf(c0, v0.w, acc.w);
            acc.x = fmaf(c1, v1.x, acc.x); acc.y = fmaf(c1, v1.y, acc.y);
            acc.z = fmaf(c1, v1.z, acc.z); acc.w = fmaf(c1, v1.w, acc.w);
        }
        if (j < m) {
            int   s0 = __shfl_sync(0xffffffffu, s, j);
            float c0 = __shfl_sync(0xffffffffu, c, j);
            float4 v0 = *(const float4*)(g_A + (size_t)s0 * HD + lane * 4);
            acc.x = fmaf(c0, v0.x, acc.x); acc.y = fmaf(c0, v0.y, acc.y);
            acc.z = fmaf(c0, v0.z, acc.z); acc.w = fmaf(c0, v0.w, acc.w);
        }
    }
    *(float4*)(g_B + (size_t)w * HD + lane * 4) = acc;
}

// ================= GAT: fused softmax + aggregation (warp per dst node) =================
__global__ __launch_bounds__(256) void k_gat_agg(const float* __restrict__ bg, int n) {
    int w = (blockIdx.x * blockDim.x + threadIdx.x) >> 5;
    if (w >= n) return;
    int lane = threadIdx.x & 31;
    int beg = g_rowptr[w], end = g_rowptr[w + 1];

    float ad_d = g_ad[w];
    float a_self = leaky(g_as[w] + ad_d);

    // pass 1: max over attention logits
    float mx = a_self;
    for (int idx = beg + lane; idx < end; idx += 32) {
        int s = g_csr_src[idx];
        mx = fmaxf(mx, leaky(g_as[s] + ad_d));
    }
    #pragma unroll
    for (int o = 16; o; o >>= 1)
        mx = fmaxf(mx, __shfl_xor_sync(0xffffffffu, mx, o));

    // pass 2: denom + weighted gather
    float wself = expf(a_self - mx);
    float denp = 0.f;
    float4 av = *(const float4*)(g_A + (size_t)w * HD + lane * 4);
    float4 acc;
    acc.x = wself * av.x; acc.y = wself * av.y;
    acc.z = wself * av.z; acc.w = wself * av.w;

    for (int j0 = beg; j0 < end; j0 += 32) {
        int idx = j0 + lane;
        int s = 0; float ww = 0.f;
        if (idx < end) {
            s = g_csr_src[idx];
            ww = expf(leaky(g_as[s] + ad_d) - mx);
            denp += ww;
        }
        int m = min(32, end - j0);
        int j = 0;
        for (; j + 1 < m; j += 2) {
            int   s0 = __shfl_sync(0xffffffffu, s, j);
            float w0 = __shfl_sync(0xffffffffu, ww, j);
            int   s1 = __shfl_sync(0xffffffffu, s, j + 1);
            float w1 = __shfl_sync(0xffffffffu, ww, j + 1);
            float4 v0 = *(const float4*)(g_A + (size_t)s0 * HD + lane * 4);
            float4 v1 = *(const float4*)(g_A + (size_t)s1 * HD + lane * 4);
            acc.x = fmaf(w0, v0.x, acc.x); acc.y = fmaf(w0, v0.y, acc.y);
            acc.z = fmaf(w0, v0.z, acc.z); acc.w = fmaf(w0, v0.w, acc.w);
            acc.x = fmaf(w1, v1.x, acc.x); acc.y = fmaf(w1, v1.y, acc.y);
            acc.z = fmaf(w1, v1.z, acc.z); acc.w = fmaf(w1, v1.w, acc.w);
        }
        if (j < m) {
            int   s0 = __shfl_sync(0xffffffffu, s, j);
            float w0 = __shfl_sync(0xffffffffu, ww, j);
            float4 v0 = *(const float4*)(g_A + (size_t)s0 * HD + lane * 4);
            acc.x = fmaf(w0, v0.x, acc.x); acc.y = fmaf(w0, v0.y, acc.y);
            acc.z = fmaf(w0, v0.z, acc.z); acc.w = fmaf(w0, v0.w, acc.w);
        }
    }
    #pragma unroll
    for (int o = 16; o; o >>= 1)
        denp += __shfl_xor_sync(0xffffffffu, denp, o);
    float inv = 1.0f / (denp + wself);

    float4 b = *(const float4*)(bg + lane * 4);
    acc.x = fmaf(acc.x, inv, b.x);
    acc.y = fmaf(acc.y, inv, b.y);
    acc.z = fmaf(acc.z, inv, b.z);
    acc.w = fmaf(acc.w, inv, b.w);
    *(float4*)(g_B + (size_t)w * HD + lane * 4) = acc;
}

// ================= final: out = relu(B) @ Wc + bc =================
__global__ __launch_bounds__(256) void k_out(const float* __restrict__ Wc,
                                             const float* __restrict__ bc,
                                             float* __restrict__ out, int n) {
    __shared__ float4 ws[512];   // Wc[128][16] as float4
    for (int i = threadIdx.x; i < 512; i += 256) ws[i] = ((const float4*)Wc)[i];
    __syncthreads();
    int i = blockIdx.x * blockDim.x + threadIdx.x;
    if (i >= n) return;
    float4 a0 = ((const float4*)bc)[0];
    float4 a1 = ((const float4*)bc)[1];
    float4 a2 = ((const float4*)bc)[2];
    float4 a3 = ((const float4*)bc)[3];
    const float4* brow = (const float4*)(g_B + (size_t)i * HD);
    #pragma unroll 4
    for (int k0 = 0; k0 < 32; k0++) {
        float4 v = brow[k0];
        v.x = fmaxf(v.x, 0.f); v.y = fmaxf(v.y, 0.f);
        v.z = fmaxf(v.z, 0.f); v.w = fmaxf(v.w, 0.f);
        float bvals[4] = {v.x, v.y, v.z, v.w};
        #pragma unroll
        for (int kk = 0; kk < 4; kk++) {
            float bv = bvals[kk];
            const float4* wp = &ws[(k0 * 4 + kk) * 4];
            float4 w0 = wp[0], w1 = wp[1], w2 = wp[2], w3 = wp[3];
            a0.x = fmaf(bv, w0.x, a0.x); a0.y = fmaf(bv, w0.y, a0.y);
            a0.z = fmaf(bv, w0.z, a0.z); a0.w = fmaf(bv, w0.w, a0.w);
            a1.x = fmaf(bv, w1.x, a1.x); a1.y = fmaf(bv, w1.y, a1.y);
            a1.z = fmaf(bv, w1.z, a1.z); a1.w = fmaf(bv, w1.w, a1.w);
            a2.x = fmaf(bv, w2.x, a2.x); a2.y = fmaf(bv, w2.y, a2.y);
            a2.z = fmaf(bv, w2.z, a2.z); a2.w = fmaf(bv, w2.w, a2.w);
            a3.x = fmaf(bv, w3.x, a3.x); a3.y = fmaf(bv, w3.y, a3.y);
            a3.z = fmaf(bv, w3.z, a3.z); a3.w = fmaf(bv, w3.w, a3.w);
        }
    }
    float4* op = (float4*)(out + (size_t)i * 16);
    op[0] = a0; op[1] = a1; op[2] = a2; op[3] = a3;
}

static inline int ceildiv(int a, int b) { return (a + b - 1) / b; }

extern "C" void kernel_launch(void* const* d_in, const int* in_sizes, int n_in,
                              void* d_out, int out_size) {
    const float* x       = (const float*)d_in[0];
    const int*   ei      = (const int*)d_in[1];
    const float* ew      = (const float*)d_in[2];
    const float* W1      = (const float*)d_in[3];
    const float* b1      = (const float*)d_in[4];
    const float* W2      = (const float*)d_in[5];
    const float* b2      = (const float*)d_in[6];
    const float* Wg      = (const float*)d_in[7];
    const float* att_src = (const float*)d_in[8];
    const float* att_dst = (const float*)d_in[9];
    const float* bg      = (const float*)d_in[10];
    const float* Wc      = (const float*)d_in[11];
    const float* bc      = (const float*)d_in[12];

    int n = in_sizes[0] / HD;
    int e = in_sizes[2];
    const int* src = ei;
    const int* dst = ei + e;

    float *dA = nullptr, *dB = nullptr;
    cudaGetSymbolAddress((void**)&dA, g_A);
    cudaGetSymbolAddress((void**)&dB, g_B);

    const int tb = 256;
    const int gb = ceildiv(n, 64);
    const int ga = ceildiv(n, 8);       // warp-per-node kernels: 8 nodes/block
    const int nb = ceildiv(n, SCAN_B);

    // ---- CSR build + normalization ----
    k_zero<<<ceildiv(n, tb), tb>>>(n);
    k_count_deg<<<ceildiv(e, tb), tb>>>(dst, ew, e);
    k_scan1<<<nb, SCAN_B>>>(n);
    k_scan2<<<1, 128>>>(nb);
    k_scan3_dinv<<<ceildiv(n, tb), tb>>>(n);
    k_fill<<<ceildiv(e, tb), tb>>>(src, dst, ew, e);

    // ---- GCN layer 1 ----
    k_gemm128<false, false><<<gb, 256>>>(x, W1, dA, nullptr, nullptr, n);
    k_gcn_agg<<<ga, 256>>>(b1, n);

    // ---- GCN layer 2 ----
    k_gemm128<true, false><<<gb, 256>>>(dB, W2, dA, nullptr, nullptr, n);
    k_gcn_agg<<<ga, 256>>>(b2, n);

    // ---- GAT (dots fused into GEMM epilogue, softmax+agg fused) ----
    k_gemm128<true, true><<<gb, 256>>>(dB, Wg, dA, att_src, att_dst, n);
    k_gat_agg<<<ga, 256>>>(bg, n);

    // ---- classifier ----
    k_out<<<ceildiv(n, tb), tb>>>(Wc, bc, (float*)d_out, n);
}